// round 16
// baseline (speedup 1.0000x reference)
#include <cuda_runtime.h>
#include <cuda_fp16.h>
#include <cstdint>
#include <cstddef>

#define P_C     16
#define W_C     8
#define F_IN_C  128
#define F_OUT_C 128
#define NPAD    100352   // padded dst count

// fp16 plane scratch: plane[kc][dst] = uint4 = 8 halfs, natural k order.
// kc 0..15 : neighbor features k = kc*8..+7 ; kc 16..31 : self features
__device__ uint4 g_plane[(size_t)32 * NPAD];

// ---------------------------------------------------------------------------
// Kernel 1: fused decode+gather+mean + h_self conversion.
// 2 dsts per warp per epoch; when both have deg==16 (common case), ALL code
// loads (2 idx LDG + 16 shfl + 16 code LDG) are issued before accumulation
// begins (MLP=16), then two pure-LDS accumulation passes run back-to-back.
// Staged in smem, flushed transposed (warp kc writes 64 consecutive dsts).
// ---------------------------------------------------------------------------
#define GW_THREADS 1024
#define GW_BLOCKS  296
// smem: 16384 half2 codebook (64 KB) + 64*33 uint4 staging (33792 B)
#define GW_SMEM (65536 + 64 * 33 * 16)

__device__ __forceinline__ uint4 pack_neigh(float4 lo, float4 hi) {
    __half2 q0 = __floats2half2_rn(lo.x, lo.y);
    __half2 q1 = __floats2half2_rn(lo.z, lo.w);
    __half2 q2 = __floats2half2_rn(hi.x, hi.y);
    __half2 q3 = __floats2half2_rn(hi.z, hi.w);
    uint4 pk;
    pk.x = *reinterpret_cast<uint32_t*>(&q0);
    pk.y = *reinterpret_cast<uint32_t*>(&q1);
    pk.z = *reinterpret_cast<uint32_t*>(&q2);
    pk.w = *reinterpret_cast<uint32_t*>(&q3);
    return pk;
}

__device__ __forceinline__ uint4 pack_self(const float* __restrict__ hself,
                                           int dst, int p) {
    const float4* hs = reinterpret_cast<const float4*>(
        hself + (size_t)dst * F_IN_C + p * 8);
    float4 a = __ldg(hs);
    float4 b = __ldg(hs + 1);
    __half2 q0 = __floats2half2_rn(a.x, a.y);
    __half2 q1 = __floats2half2_rn(a.z, a.w);
    __half2 q2 = __floats2half2_rn(b.x, b.y);
    __half2 q3 = __floats2half2_rn(b.z, b.w);
    uint4 pk;
    pk.x = *reinterpret_cast<uint32_t*>(&q0);
    pk.y = *reinterpret_cast<uint32_t*>(&q1);
    pk.z = *reinterpret_cast<uint32_t*>(&q2);
    pk.w = *reinterpret_cast<uint32_t*>(&q3);
    return pk;
}

// accumulate 16 entries (8 steps) from smem codebook; returns combined fp32
// (valid on lanes<16). Warp-collective (shfl_down).
__device__ __forceinline__ void accum16(const __half2* __restrict__ cb_p,
                                        const int c[8], float4& lo, float4& hi) {
    __half2 a0 = __float2half2_rn(0.f), a1 = a0, a2 = a0, a3 = a0;
#pragma unroll
    for (int s = 0; s < 8; s++) {
        uint4 v = *reinterpret_cast<const uint4*>(cb_p + c[s] * 4);
        a0 = __hadd2(a0, *reinterpret_cast<__half2*>(&v.x));
        a1 = __hadd2(a1, *reinterpret_cast<__half2*>(&v.y));
        a2 = __hadd2(a2, *reinterpret_cast<__half2*>(&v.z));
        a3 = __hadd2(a3, *reinterpret_cast<__half2*>(&v.w));
    }
    uint32_t u0 = *reinterpret_cast<uint32_t*>(&a0);
    uint32_t u1 = *reinterpret_cast<uint32_t*>(&a1);
    uint32_t u2 = *reinterpret_cast<uint32_t*>(&a2);
    uint32_t u3 = *reinterpret_cast<uint32_t*>(&a3);
    uint32_t q0 = __shfl_down_sync(0xffffffffu, u0, 16);
    uint32_t q1 = __shfl_down_sync(0xffffffffu, u1, 16);
    uint32_t q2 = __shfl_down_sync(0xffffffffu, u2, 16);
    uint32_t q3 = __shfl_down_sync(0xffffffffu, u3, 16);
    float2 f0 = __half22float2(*reinterpret_cast<__half2*>(&u0));
    float2 f1 = __half22float2(*reinterpret_cast<__half2*>(&u1));
    float2 f2 = __half22float2(*reinterpret_cast<__half2*>(&u2));
    float2 f3 = __half22float2(*reinterpret_cast<__half2*>(&u3));
    float2 g0 = __half22float2(*reinterpret_cast<__half2*>(&q0));
    float2 g1 = __half22float2(*reinterpret_cast<__half2*>(&q1));
    float2 g2 = __half22float2(*reinterpret_cast<__half2*>(&q2));
    float2 g3 = __half22float2(*reinterpret_cast<__half2*>(&q3));
    const float s16 = 1.0f / 16.0f;
    lo = make_float4((f0.x + g0.x) * s16, (f0.y + g0.y) * s16,
                     (f1.x + g1.x) * s16, (f1.y + g1.y) * s16);
    hi = make_float4((f2.x + g2.x) * s16, (f2.y + g2.y) * s16,
                     (f3.x + g3.x) * s16, (f3.y + g3.y) * s16);
}

__global__ __launch_bounds__(GW_THREADS, 2) void gather_fused_kernel(
    const int* __restrict__ codes,
    const int* __restrict__ indices,
    const int* __restrict__ indptr,
    const float* __restrict__ codebook,
    const float* __restrict__ hself,
    int n_dst) {
    extern __shared__ __half2 cbh[];                      // [16384] half2 = 64 KB
    uint4* stag = reinterpret_cast<uint4*>(cbh + 16384);  // [64][33] uint4

    int tid  = threadIdx.x;
    int lane = tid & 31;
    int wid  = tid >> 5;

#pragma unroll
    for (int i = 0; i < 4; i++) {
        int blk = i * GW_THREADS + tid;
        const float4* s = reinterpret_cast<const float4*>(codebook + blk * 8);
        float4 a = __ldg(s);
        float4 b = __ldg(s + 1);
        __half2 h0 = __floats2half2_rn(a.x, a.y);
        __half2 h1 = __floats2half2_rn(a.z, a.w);
        __half2 h2 = __floats2half2_rn(b.x, b.y);
        __half2 h3 = __floats2half2_rn(b.z, b.w);
        uint4 pk;
        pk.x = *reinterpret_cast<uint32_t*>(&h0);
        pk.y = *reinterpret_cast<uint32_t*>(&h1);
        pk.z = *reinterpret_cast<uint32_t*>(&h2);
        pk.w = *reinterpret_cast<uint32_t*>(&h3);
        reinterpret_cast<uint4*>(cbh)[blk] = pk;
    }
    __syncthreads();

    int p = lane & 15;
    int h = lane >> 4;
    const __half2* cb_p = cbh + (p << 10);

    int stride = GW_BLOCKS * 64;
    for (int base = blockIdx.x * 64; base < n_dst; base += stride) {
        int dst0 = base + wid;
        int dst1 = base + 32 + wid;
        bool v0 = dst0 < n_dst;
        bool v1 = dst1 < n_dst;
        int start0 = 0, deg0 = -1, start1 = 0, deg1 = -1;
        if (v0) { start0 = __ldg(indptr + dst0); deg0 = __ldg(indptr + dst0 + 1) - start0; }
        if (v1) { start1 = __ldg(indptr + dst1); deg1 = __ldg(indptr + dst1 + 1) - start1; }

        if (v0 && v1 && deg0 == 16 && deg1 == 16) {
            // ---- dual fast path: front-load ALL code fetches ----
            int i0 = __ldg(indices + start0 + (lane & 15));
            int i1 = __ldg(indices + start1 + (lane & 15));
            int c0[8], c1[8];
#pragma unroll
            for (int s = 0; s < 8; s++) {
                int s0 = __shfl_sync(0xffffffffu, i0, 2 * s + h);
                c0[s] = __ldg(codes + s0 * P_C + p);
                int s1 = __shfl_sync(0xffffffffu, i1, 2 * s + h);
                c1[s] = __ldg(codes + s1 * P_C + p);
            }
            float4 lo0, hi0, lo1, hi1;
            accum16(cb_p, c0, lo0, hi0);
            accum16(cb_p, c1, lo1, hi1);

            uint4 pk0, pk1;
            if (lane < 16) {
                pk0 = pack_neigh(lo0, hi0);
                pk1 = pack_neigh(lo1, hi1);
            } else {
                pk0 = pack_self(hself, dst0, p);
                pk1 = pack_self(hself, dst1, p);
            }
            stag[wid * 33 + lane]        = pk0;
            stag[(32 + wid) * 33 + lane] = pk1;
        } else {
            // ---- generic path, per dst ----
#pragma unroll
            for (int u = 0; u < 2; u++) {
                int dst   = u ? dst1 : dst0;
                int start = u ? start1 : start0;
                int deg   = u ? deg1 : deg0;
                if (dst >= n_dst) continue;

                float4 lo, hi;
                if (deg == 16) {
                    int my_idx = __ldg(indices + start + (lane & 15));
                    int c[8];
#pragma unroll
                    for (int s = 0; s < 8; s++) {
                        int src = __shfl_sync(0xffffffffu, my_idx, 2 * s + h);
                        c[s] = __ldg(codes + src * P_C + p);
                    }
                    accum16(cb_p, c, lo, hi);
                } else {
                    float4 acc = make_float4(0.f, 0.f, 0.f, 0.f);
                    for (int e = 0; e < deg; e++) {
                        int src = __ldg(indices + start + e);
                        int c = __ldg(codes + src * P_C + p);
                        __half2 a = cb_p[c * 4 + h * 2];
                        __half2 b = cb_p[c * 4 + h * 2 + 1];
                        float2 fa = __half22float2(a), fb = __half22float2(b);
                        acc.x += fa.x; acc.y += fa.y; acc.z += fb.x; acc.w += fb.y;
                    }
                    float s = 1.0f / fmaxf((float)deg, 1.0f);
                    acc.x *= s; acc.y *= s; acc.z *= s; acc.w *= s;
                    float4 acch;
                    acch.x = __shfl_down_sync(0xffffffffu, acc.x, 16);
                    acch.y = __shfl_down_sync(0xffffffffu, acc.y, 16);
                    acch.z = __shfl_down_sync(0xffffffffu, acc.z, 16);
                    acch.w = __shfl_down_sync(0xffffffffu, acc.w, 16);
                    lo = acc; hi = acch;
                }
                uint4 pk = (lane < 16) ? pack_neigh(lo, hi)
                                       : pack_self(hself, dst, p);
                stag[(u * 32 + wid) * 33 + lane] = pk;
            }
        }
        __syncthreads();
        // flush: warp kc=wid writes 64 consecutive dsts of its plane
#pragma unroll
        for (int u = 0; u < 2; u++) {
            int d = base + u * 32 + lane;
            if (d < n_dst)
                g_plane[(size_t)wid * NPAD + d] = stag[(u * 32 + lane) * 33 + wid];
        }
        __syncthreads();
    }
}

// ---------------------------------------------------------------------------
// Kernel 2: fp16 mma.sync (m16n8k16) GEMM. 512 thr, 16 warps: 8 M x 2 N;
// warp tile 32(M) x 64(N); CTA tile 256(M) x 128(N). A register-pipelined
// one kb ahead; B fragments register-pipelined one nf ahead (LDS latency
// hidden under the 2 MMAs of the current nf).
// ---------------------------------------------------------------------------
__device__ __forceinline__ void mma_f16(float* d, const uint32_t* a, const uint32_t* b) {
    asm volatile(
        "mma.sync.aligned.m16n8k16.row.col.f32.f16.f16.f32 "
        "{%0,%1,%2,%3}, {%4,%5,%6,%7}, {%8,%9}, {%0,%1,%2,%3};"
        : "+f"(d[0]), "+f"(d[1]), "+f"(d[2]), "+f"(d[3])
        : "r"(a[0]), "r"(a[1]), "r"(a[2]), "r"(a[3]), "r"(b[0]), "r"(b[1]));
}

#define GT        512
#define GEMM_GRID 148
#define SMB_TOT (16 * 16 * 2 * 32 * 4)

__device__ __forceinline__ void load_a_kb(uint32_t a[2][4],
                                          const uint32_t* __restrict__ plane,
                                          int kb, int r0w, int lane) {
#pragma unroll
    for (int mi = 0; mi < 2; mi++) {
        int rb = r0w + mi * 16;
        size_t b0 = ((size_t)(2 * kb) * NPAD + rb) * 4;
        size_t b1 = b0 + (size_t)NPAD * 4;
        a[mi][0] = __ldg(plane + b0 + lane);
        a[mi][1] = __ldg(plane + b0 + 32 + lane);
        a[mi][2] = __ldg(plane + b1 + lane);
        a[mi][3] = __ldg(plane + b1 + 32 + lane);
    }
}

__global__ __launch_bounds__(GT, 1) void gemm_mma_kernel(
    const float* __restrict__ Wn,
    const float* __restrict__ Ws,
    const float* __restrict__ bias,
    float* __restrict__ out,
    int n_dst) {
    extern __shared__ uint32_t sB[];
    int tid  = threadIdx.x;
    int wid  = tid >> 5;
    int lane = tid & 31;
    int wm   = wid >> 1;   // 0..7 : rows wm*32..+31
    int wn   = wid & 1;    // 0..1 : cols wn*64..+63

    // ---- stage B once: packed half2 fp16 fragments ----
#pragma unroll
    for (int i = 0; i < 32; i++) {
        int slot   = i * GT + tid;
        int l      = slot & 31;
        int half_  = (slot >> 5) & 1;
        int kb     = (slot >> 6) & 15;
        int nblock = slot >> 10;
        int n  = nblock * 8 + (l >> 2);
        int k0 = kb * 16 + half_ * 8 + (l & 3) * 2;
        float flo = (k0     < 128) ? __ldg(Wn + n * 128 + k0)     : __ldg(Ws + n * 128 + k0 - 128);
        float fhi = (k0 + 1 < 128) ? __ldg(Wn + n * 128 + k0 + 1) : __ldg(Ws + n * 128 + k0 - 127);
        __half2 hp = __floats2half2_rn(flo, fhi);
        sB[slot] = *reinterpret_cast<uint32_t*>(&hp);
    }
    __syncthreads();

    int colq = (lane & 3) * 2;
    int rowq = lane >> 2;

    const uint32_t* plane = reinterpret_cast<const uint32_t*>(g_plane);
    int ntiles = (n_dst + 255) >> 8;

    for (int tile = blockIdx.x; tile < ntiles; tile += gridDim.x) {
        int m0  = tile << 8;
        int r0w = m0 + wm * 32;

        float acc[2][8][4];
#pragma unroll
        for (int mi = 0; mi < 2; mi++)
#pragma unroll
            for (int j = 0; j < 8; j++)
#pragma unroll
                for (int r = 0; r < 4; r++) acc[mi][j][r] = 0.f;

        uint32_t a[2][4];
        load_a_kb(a, plane, 0, r0w, lane);

        uint32_t bf[2], bfn[2];
        {
            int nb = wn * 8;
            bfn[0] = sB[((nb * 16 + 0) * 2 + 0) * 32 + lane];
            bfn[1] = sB[((nb * 16 + 0) * 2 + 1) * 32 + lane];
        }

#pragma unroll
        for (int kb = 0; kb < 16; kb++) {
            uint32_t an[2][4];
            if (kb < 15) load_a_kb(an, plane, kb + 1, r0w, lane);
#pragma unroll
            for (int nf = 0; nf < 8; nf++) {
                bf[0] = bfn[0];
                bf[1] = bfn[1];
                // prefetch next fragment (next nf, or next kb's nf=0)
                int nnf = (nf == 7) ? 0 : nf + 1;
                int nkb = (nf == 7) ? ((kb < 15) ? kb + 1 : kb) : kb;
                int nb  = wn * 8 + nnf;
                bfn[0] = sB[((nb * 16 + nkb) * 2 + 0) * 32 + lane];
                bfn[1] = sB[((nb * 16 + nkb) * 2 + 1) * 32 + lane];
                mma_f16(acc[0][nf], a[0], bf);
                mma_f16(acc[1][nf], a[1], bf);
            }
            if (kb < 15) {
#pragma unroll
                for (int mi = 0; mi < 2; mi++)
#pragma unroll
                    for (int r = 0; r < 4; r++) a[mi][r] = an[mi][r];
            }
        }

        // ---- epilogue: bias + store ----
#pragma unroll
        for (int mi = 0; mi < 2; mi++) {
            int r0 = r0w + mi * 16 + rowq;
            int r1 = r0 + 8;
#pragma unroll
            for (int nf = 0; nf < 8; nf++) {
                int col = wn * 64 + nf * 8 + colq;
                float2 b2 = *reinterpret_cast<const float2*>(bias + col);
                if (r0 < n_dst) {
                    float2 o = make_float2(acc[mi][nf][0] + b2.x, acc[mi][nf][1] + b2.y);
                    *reinterpret_cast<float2*>(out + (size_t)r0 * F_OUT_C + col) = o;
                }
                if (r1 < n_dst) {
                    float2 o = make_float2(acc[mi][nf][2] + b2.x, acc[mi][nf][3] + b2.y);
                    *reinterpret_cast<float2*>(out + (size_t)r1 * F_OUT_C + col) = o;
                }
            }
        }
    }
}

// ---------------------------------------------------------------------------
// Launch
// ---------------------------------------------------------------------------
extern "C" void kernel_launch(void* const* d_in, const int* in_sizes, int n_in,
                              void* d_out, int out_size) {
    const int*   codes    = (const int*)d_in[0];
    const int*   indices  = (const int*)d_in[1];
    const int*   indptr   = (const int*)d_in[2];
    const float* h_self   = (const float*)d_in[3];
    const float* codebook = (const float*)d_in[4];
    const float* Wn       = (const float*)d_in[5];
    const float* Ws       = (const float*)d_in[6];
    const float* b_self   = (const float*)d_in[7];
    float* out = (float*)d_out;

    int n_dst = in_sizes[2] - 1;

    {
        cudaFuncSetAttribute(gather_fused_kernel,
                             cudaFuncAttributeMaxDynamicSharedMemorySize, GW_SMEM);
        gather_fused_kernel<<<GW_BLOCKS, GW_THREADS, GW_SMEM>>>(
            codes, indices, indptr, codebook, h_self, n_dst);
    }
    {
        cudaFuncSetAttribute(gemm_mma_kernel,
                             cudaFuncAttributeMaxDynamicSharedMemorySize, SMB_TOT);
        gemm_mma_kernel<<<GEMM_GRID, GT, SMB_TOT>>>(
            Wn, Ws, b_self, out, n_dst);
    }
}